// round 10
// baseline (speedup 1.0000x reference)
#include <cuda_runtime.h>
#include <math.h>

#define TB   8
#define TD   512
#define TDD  1024
#define TT   4096
#define NCTA 128
#define CJ   8        // h cols per CTA
#define CI   4        // p cols per CTA
#define NTHR 256
#define NWARP 8

__device__ float gMem[TB * TD];    // recurrent state (in place; schedule-proven safe)
__device__ float gH[TB * TDD];     // hidden activations (in place)
__device__ __align__(256) unsigned gBarH[64];
__device__ __align__(256) unsigned gBarM[64];

__global__ void init_scratch() {
    int t = blockIdx.x * blockDim.x + threadIdx.x;
    if (t < TB * TD) gMem[t] = 0.0f;
    if (t < 64) { gBarH[t] = 0u; gBarM[t] = 0u; }
}

__device__ __forceinline__ void fma2(unsigned long long& acc,
                                     unsigned long long a,
                                     unsigned long long b) {
    asm volatile("fma.rn.f32x2 %0, %1, %2, %0;" : "+l"(acc) : "l"(a), "l"(b));
}
__device__ __forceinline__ float2 u2f(unsigned long long v) {
    float2 f;
    asm("mov.b64 {%0,%1}, %2;" : "=f"(f.x), "=f"(f.y) : "l"(v));
    return f;
}
__device__ __forceinline__ ulonglong2 ldg128_cg(const void* p) {
    ulonglong2 v;
    asm volatile("ld.global.cg.v2.u64 {%0,%1}, [%2];"
                 : "=l"(v.x), "=l"(v.y) : "l"(p));
    return v;
}
__device__ __forceinline__ ulonglong2 ldg128_nc(const void* p) {
    ulonglong2 v;
    asm volatile("ld.global.nc.v2.u64 {%0,%1}, [%2];"
                 : "=l"(v.x), "=l"(v.y) : "l"(p));
    return v;
}
__device__ __forceinline__ void stg_cg(float* p, float v) {
    asm volatile("st.global.cg.f32 [%0], %1;" :: "l"(p), "f"(v) : "memory");
}
__device__ __forceinline__ void bar_arrive(unsigned* ctr) {
    unsigned one = 1u;
    asm volatile("red.release.gpu.global.add.u32 [%0], %1;"
                 :: "l"(ctr), "r"(one) : "memory");
}
__device__ __forceinline__ void bar_spin(const unsigned* ctr, unsigned tgt) {
    unsigned v;
    do {
        asm volatile("ld.relaxed.gpu.global.u32 %0, [%1];"
                     : "=r"(v) : "l"(ctr) : "memory");
    } while (v < tgt);
}

__global__ void __launch_bounds__(NTHR, 1)
sys2_kernel(const float* __restrict__ x,
            const float* __restrict__ W1,
            const float* __restrict__ b1,
            const float* __restrict__ W2,
            const float* __restrict__ b2,
            float* __restrict__ y)
{
    extern __shared__ float smem[];
    float* sW1   = smem;                     // CJ*TDD (32 KB)
    float* sW2   = sW1 + CJ * TDD;           // CI*TDD (16 KB)
    float* sPart = sW2 + CI * TDD;           // NWARP*64 = 512
    float* sB1   = sPart + NWARP * 64;       // CJ
    float* sB2   = sB1 + CJ;                 // CI

    const int cta  = blockIdx.x;
    const int tid  = threadIdx.x;
    const int w    = tid >> 5;
    const int lane = tid & 31;
    const int bp   = lane >> 3;   // batch pair base: owns b=bp and b=bp+4
    const int kq   = lane & 7;    // k-phase (8 per warp)
    const int jbase = cta * CJ;
    const int ibase = cta * CI;

    {
        const float4* g1 = (const float4*)(W1 + (size_t)jbase * TDD);
        float4* s1 = (float4*)sW1;
        for (int idx = tid; idx < CJ * TDD / 4; idx += NTHR) s1[idx] = g1[idx];
        const float4* g2 = (const float4*)(W2 + (size_t)ibase * TDD);
        float4* s2 = (float4*)sW2;
        for (int idx = tid; idx < CI * TDD / 4; idx += NTHR) s2[idx] = g2[idx];
        if (tid < CJ) sB1[tid] = b1[jbase + tid];
        if (tid < CI) sB2[tid] = b2[ibase + tid];
    }
    __syncthreads();

    float memReg = 0.0f;   // tid<32 owns output (bb=tid>>2, ii=tid&3)

    // GEMM1 k-slice: 8 consecutive k per lane, warp covers 64
    const int k1 = (w << 6) + (kq << 3);
    // GEMM2 k-slice: 16 consecutive k per lane, warp covers 128
    const int k2 = (w << 7) + (kq << 4);

    // preload x(0): [bl][half], 4 LDG.128
    ulonglong2 ex[2][2];
#pragma unroll
    for (int bl = 0; bl < 2; ++bl) {
        const float* xr = x + ((size_t)(bp + 4 * bl) * TT) * TD + k1;
        ex[bl][0] = ldg128_nc(xr);
        ex[bl][1] = ldg128_nc(xr + 4);
    }

    for (int t = 0; t < TT; ++t) {
        // ===== Phase 1: h = gelu(W1 @ [x_t ; mem] + b1), j-slice =====
        unsigned long long ac[CJ][2];
#pragma unroll
        for (int j = 0; j < CJ; ++j) { ac[j][0] = 0ull; ac[j][1] = 0ull; }

        // x-half part A (j=0..3) — overlaps the spin below
#pragma unroll
        for (int j = 0; j < 4; ++j) {
            const ulonglong2 wv0 = *(const ulonglong2*)(sW1 + j * TDD + k1);
            const ulonglong2 wv1 = *(const ulonglong2*)(sW1 + j * TDD + k1 + 4);
#pragma unroll
            for (int bl = 0; bl < 2; ++bl) {
                fma2(ac[j][bl], wv0.x, ex[bl][0].x);
                fma2(ac[j][bl], wv0.y, ex[bl][0].y);
                fma2(ac[j][bl], wv1.x, ex[bl][1].x);
                fma2(ac[j][bl], wv1.y, ex[bl][1].y);
            }
        }

        if (t > 0 && tid == 0) bar_spin(&gBarM[0], (unsigned)t * NCTA);
        __syncthreads();                       // S1: mem(t-1) visible chip-wide

        // mem loads in flight under x-half part B
        ulonglong2 em[2][2];
#pragma unroll
        for (int bl = 0; bl < 2; ++bl) {
            const float* mr = gMem + (bp + 4 * bl) * TD + k1;
            em[bl][0] = ldg128_cg(mr);
            em[bl][1] = ldg128_cg(mr + 4);
        }

#pragma unroll
        for (int j = 4; j < CJ; ++j) {
            const ulonglong2 wv0 = *(const ulonglong2*)(sW1 + j * TDD + k1);
            const ulonglong2 wv1 = *(const ulonglong2*)(sW1 + j * TDD + k1 + 4);
#pragma unroll
            for (int bl = 0; bl < 2; ++bl) {
                fma2(ac[j][bl], wv0.x, ex[bl][0].x);
                fma2(ac[j][bl], wv0.y, ex[bl][0].y);
                fma2(ac[j][bl], wv1.x, ex[bl][1].x);
                fma2(ac[j][bl], wv1.y, ex[bl][1].y);
            }
        }
        // mem-half (j=0..7)
#pragma unroll
        for (int j = 0; j < CJ; ++j) {
            const ulonglong2 wv0 = *(const ulonglong2*)(sW1 + j * TDD + TD + k1);
            const ulonglong2 wv1 = *(const ulonglong2*)(sW1 + j * TDD + TD + k1 + 4);
#pragma unroll
            for (int bl = 0; bl < 2; ++bl) {
                fma2(ac[j][bl], wv0.x, em[bl][0].x);
                fma2(ac[j][bl], wv0.y, em[bl][0].y);
                fma2(ac[j][bl], wv1.x, em[bl][1].x);
                fma2(ac[j][bl], wv1.y, em[bl][1].y);
            }
        }
        // reduce over kq (8 lanes: xor 1,2,4), store per (j, b)
#pragma unroll
        for (int j = 0; j < CJ; ++j) {
#pragma unroll
            for (int bl = 0; bl < 2; ++bl) {
                const float2 f = u2f(ac[j][bl]);
                float s = f.x + f.y;
                s += __shfl_xor_sync(0xffffffffu, s, 1);
                s += __shfl_xor_sync(0xffffffffu, s, 2);
                s += __shfl_xor_sync(0xffffffffu, s, 4);
                if (kq == 0) sPart[(w << 6) + ((bp + 4 * bl) << 3) + j] = s;
            }
        }
        __syncthreads();                       // S2

        // h-epilogue: threads 0..63, 1 output each
        if (tid < TB * CJ) {
            const int bb = tid >> 3, jj = tid & 7;
            float s = sB1[jj];
#pragma unroll
            for (int ww = 0; ww < NWARP; ++ww) s += sPart[(ww << 6) + tid];
            const float hval = 0.5f * s * (1.0f + erff(s * 0.70710678118654752f));
            stg_cg(&gH[bb * TDD + jbase + jj], hval);
        }
        __syncthreads();                       // S2b
        if (tid == 0) bar_arrive(&gBarH[0]);

        // prefetch x(t+1) — overlaps the h-barrier wait
        {
            const int tn = (t + 1 < TT) ? (t + 1) : t;
#pragma unroll
            for (int bl = 0; bl < 2; ++bl) {
                const float* xr = x + ((size_t)(bp + 4 * bl) * TT + tn) * TD + k1;
                ex[bl][0] = ldg128_nc(xr);
                ex[bl][1] = ldg128_nc(xr + 4);
            }
        }

        if (tid == 0) bar_spin(&gBarH[0], (unsigned)(t + 1) * NCTA);
        __syncthreads();                       // S3: h(t) visible chip-wide

        // ===== Phase 2: p = W2 @ h + b2 ; gated mem update, i-slice =====
        ulonglong2 eh[2][4];
#pragma unroll
        for (int bl = 0; bl < 2; ++bl) {
            const float* hr = gH + (bp + 4 * bl) * TDD + k2;
            eh[bl][0] = ldg128_cg(hr);
            eh[bl][1] = ldg128_cg(hr + 4);
            eh[bl][2] = ldg128_cg(hr + 8);
            eh[bl][3] = ldg128_cg(hr + 12);
        }

        unsigned long long pc[CI][2];
#pragma unroll
        for (int i = 0; i < CI; ++i) { pc[i][0] = 0ull; pc[i][1] = 0ull; }
#pragma unroll
        for (int i = 0; i < CI; ++i) {
            const float* wr = sW2 + i * TDD + k2;
            const ulonglong2 wv0 = *(const ulonglong2*)(wr);
            const ulonglong2 wv1 = *(const ulonglong2*)(wr + 4);
            const ulonglong2 wv2 = *(const ulonglong2*)(wr + 8);
            const ulonglong2 wv3 = *(const ulonglong2*)(wr + 12);
#pragma unroll
            for (int bl = 0; bl < 2; ++bl) {
                fma2(pc[i][bl], wv0.x, eh[bl][0].x);
                fma2(pc[i][bl], wv0.y, eh[bl][0].y);
                fma2(pc[i][bl], wv1.x, eh[bl][1].x);
                fma2(pc[i][bl], wv1.y, eh[bl][1].y);
                fma2(pc[i][bl], wv2.x, eh[bl][2].x);
                fma2(pc[i][bl], wv2.y, eh[bl][2].y);
                fma2(pc[i][bl], wv3.x, eh[bl][3].x);
                fma2(pc[i][bl], wv3.y, eh[bl][3].y);
            }
        }
#pragma unroll
        for (int i = 0; i < CI; ++i) {
#pragma unroll
            for (int bl = 0; bl < 2; ++bl) {
                const float2 f = u2f(pc[i][bl]);
                float s = f.x + f.y;
                s += __shfl_xor_sync(0xffffffffu, s, 1);
                s += __shfl_xor_sync(0xffffffffu, s, 2);
                s += __shfl_xor_sync(0xffffffffu, s, 4);
                if (kq == 0) sPart[(w << 5) + ((bp + 4 * bl) << 2) + i] = s;
            }
        }
        __syncthreads();                       // S4

        // mem-epilogue: threads 0..31, 1 output each
        if (tid < TB * CI) {
            const int bb = tid >> 2, ii = tid & 3;
            float p = sB2[ii];
#pragma unroll
            for (int ww = 0; ww < NWARP; ++ww) p += sPart[(ww << 5) + tid];
            const float g = 1.0f / (1.0f + expf(-p));
            memReg = fmaf(p - memReg, g, memReg);
            stg_cg(&gMem[bb * TD + ibase + ii], memReg);
            y[((size_t)bb * TT + t) * TD + ibase + ii] = memReg;
        }
        __syncthreads();                       // S4b
        if (tid == 0) bar_arrive(&gBarM[0]);
    }
}

extern "C" void kernel_launch(void* const* d_in, const int* in_sizes, int n_in,
                              void* d_out, int out_size) {
    const float* x  = (const float*)d_in[0];
    const float* W1 = (const float*)d_in[1];
    const float* b1 = (const float*)d_in[2];
    const float* W2 = (const float*)d_in[3];
    const float* b2 = (const float*)d_in[4];
    float* y = (float*)d_out;

    const size_t SMEM_BYTES =
        (CJ * TDD + CI * TDD + NWARP * 64 + CJ + CI) * sizeof(float);
    cudaFuncSetAttribute(sys2_kernel,
                         cudaFuncAttributeMaxDynamicSharedMemorySize,
                         (int)SMEM_BYTES);

    init_scratch<<<(TB * TD + 255) / 256, 256>>>();
    sys2_kernel<<<NCTA, NTHR, SMEM_BYTES>>>(x, W1, b1, W2, b2, y);
}